// round 1
// baseline (speedup 1.0000x reference)
#include <cuda_runtime.h>
#include <math.h>

// ---------------------------------------------------------------------------
// SelfAttention: O = softmax_causal((xWq+bq)(xWk+bk)^T / sqrt(dq)) (xWv+bv)
// n=4096, d_in=1024, d_q=1024, d_v=1024, fp32.
//
// Round 0: pure fp32 FMA-pipe implementation.
//   K1: fused QKV projection GEMM (128x128x16 tiles, 8x8/thread)
//   K2: S = Q K^T * scale  (NT GEMM, lower-triangular tiles only)
//   K3: in-place causal row softmax on S (+ zero-fill to 128-boundary)
//   K4: O = P V            (NN GEMM, per-row-tile k-limit = causal skip)
// ---------------------------------------------------------------------------

#define N_TOKEN 4096
#define D_IN    1024
#define D_QK    1024
#define D_V     1024

static_assert(N_TOKEN % 128 == 0 && D_IN % 16 == 0 && D_QK % 128 == 0, "tiling");

// Scratch (allocation-free rule: __device__ globals).
__device__ float g_Q[N_TOKEN * D_QK];
__device__ float g_K[N_TOKEN * D_QK];
__device__ float g_V[N_TOKEN * D_V];
__device__ float g_S[(size_t)N_TOKEN * N_TOKEN];   // scores, then probabilities (in place)

constexpr int BM = 128;
constexpr int BN = 128;
constexpr int BK = 16;
constexpr int NTHREADS = 256;
constexpr int LDS_PAD = 132;   // 132 floats/row: keeps float4 alignment, breaks conflicts

// Load a [BM x BK] tile of row-major A (lda) transposed into As[k][m].
__device__ __forceinline__ void load_tileA_trans(float (*As)[LDS_PAD],
                                                 const float* __restrict__ A,
                                                 int lda, int r0, int k0) {
    int t  = threadIdx.x;
    int r  = t >> 2;      // 0..63
    int cg = t & 3;       // 0..3 -> float4 within the 16-wide k slab
#pragma unroll
    for (int it = 0; it < 2; ++it) {
        int row = r + it * 64;
        float4 v = *reinterpret_cast<const float4*>(
            &A[(size_t)(r0 + row) * lda + k0 + cg * 4]);
        As[cg * 4 + 0][row] = v.x;
        As[cg * 4 + 1][row] = v.y;
        As[cg * 4 + 2][row] = v.z;
        As[cg * 4 + 3][row] = v.w;
    }
}

// Load a [BK x BN] tile of row-major B (ldb) straight into Bs[k][n].
__device__ __forceinline__ void load_tileB_nn(float (*Bs)[LDS_PAD],
                                              const float* __restrict__ B,
                                              int ldb, int k0, int c0) {
    int t = threadIdx.x;
#pragma unroll
    for (int it = 0; it < 2; ++it) {
        int idx = t + it * NTHREADS;   // 0..511 over 16 rows x 32 float4
        int row = idx >> 5;
        int c4  = idx & 31;
        float4 v = *reinterpret_cast<const float4*>(
            &B[(size_t)(k0 + row) * ldb + c0 + c4 * 4]);
        *reinterpret_cast<float4*>(&Bs[row][c4 * 4]) = v;
    }
}

// 8x8 accumulate over one BK slab. Fragments are split halves (conflict-free).
__device__ __forceinline__ void compute_tile(const float (*As)[LDS_PAD],
                                             const float (*Bs)[LDS_PAD],
                                             float acc[8][8], int ty4, int tx4) {
#pragma unroll
    for (int k = 0; k < BK; ++k) {
        float4 a0 = *reinterpret_cast<const float4*>(&As[k][ty4]);
        float4 a1 = *reinterpret_cast<const float4*>(&As[k][64 + ty4]);
        float4 b0 = *reinterpret_cast<const float4*>(&Bs[k][tx4]);
        float4 b1 = *reinterpret_cast<const float4*>(&Bs[k][64 + tx4]);
        float av[8] = {a0.x, a0.y, a0.z, a0.w, a1.x, a1.y, a1.z, a1.w};
        float bv[8] = {b0.x, b0.y, b0.z, b0.w, b1.x, b1.y, b1.z, b1.w};
#pragma unroll
        for (int ii = 0; ii < 8; ++ii)
#pragma unroll
            for (int jj = 0; jj < 8; ++jj)
                acc[ii][jj] += av[ii] * bv[jj];
    }
}

__device__ __forceinline__ int frag_sel(int base4, int ii) {
    return (ii < 4) ? (base4 + ii) : (64 + base4 + (ii - 4));
}

// --------------------------- K1: QKV projections ---------------------------
__global__ __launch_bounds__(NTHREADS)
void qkv_kernel(const float* __restrict__ x,
                const float* __restrict__ Wq, const float* __restrict__ bq,
                const float* __restrict__ Wk, const float* __restrict__ bk,
                const float* __restrict__ Wv, const float* __restrict__ bv) {
    __shared__ float As[BK][LDS_PAD];
    __shared__ float Bs[BK][LDS_PAD];

    const float* W; const float* bias; float* C;
    if (blockIdx.z == 0)      { W = Wq; bias = bq; C = g_Q; }
    else if (blockIdx.z == 1) { W = Wk; bias = bk; C = g_K; }
    else                      { W = Wv; bias = bv; C = g_V; }

    int r0 = blockIdx.y * BM;
    int c0 = blockIdx.x * BN;
    int ty4 = (threadIdx.x >> 4) * 4;
    int tx4 = (threadIdx.x & 15) * 4;

    float acc[8][8] = {};
    for (int k0 = 0; k0 < D_IN; k0 += BK) {
        load_tileA_trans(As, x, D_IN, r0, k0);
        load_tileB_nn(Bs, W, D_QK, k0, c0);
        __syncthreads();
        compute_tile(As, Bs, acc, ty4, tx4);
        __syncthreads();
    }

    float4 bl = *reinterpret_cast<const float4*>(&bias[c0 + tx4]);
    float4 bh = *reinterpret_cast<const float4*>(&bias[c0 + 64 + tx4]);
#pragma unroll
    for (int ii = 0; ii < 8; ++ii) {
        int row = r0 + frag_sel(ty4, ii);
        float4 v0 = make_float4(acc[ii][0] + bl.x, acc[ii][1] + bl.y,
                                acc[ii][2] + bl.z, acc[ii][3] + bl.w);
        float4 v1 = make_float4(acc[ii][4] + bh.x, acc[ii][5] + bh.y,
                                acc[ii][6] + bh.z, acc[ii][7] + bh.w);
        *reinterpret_cast<float4*>(&C[(size_t)row * D_QK + c0 + tx4])      = v0;
        *reinterpret_cast<float4*>(&C[(size_t)row * D_QK + c0 + 64 + tx4]) = v1;
    }
}

// --------------------------- K2: S = Q K^T * scale -------------------------
__global__ __launch_bounds__(NTHREADS)
void scores_kernel() {
    // Lower-triangular tiles only (tile col offset <= tile row offset).
    if (blockIdx.x > blockIdx.y) return;

    __shared__ float As[BK][LDS_PAD];
    __shared__ float Bs[BK][LDS_PAD];

    int r0 = blockIdx.y * BM;   // query rows
    int c0 = blockIdx.x * BN;   // key rows
    int ty4 = (threadIdx.x >> 4) * 4;
    int tx4 = (threadIdx.x & 15) * 4;

    const float scale = 1.0f / sqrtf((float)D_QK);

    float acc[8][8] = {};
    for (int k0 = 0; k0 < D_QK; k0 += BK) {
        load_tileA_trans(As, g_Q, D_QK, r0, k0);
        load_tileA_trans(Bs, g_K, D_QK, c0, k0);   // NT: K tile also transposed
        __syncthreads();
        compute_tile(As, Bs, acc, ty4, tx4);
        __syncthreads();
    }

#pragma unroll
    for (int ii = 0; ii < 8; ++ii) {
        int row = r0 + frag_sel(ty4, ii);
        float4 v0 = make_float4(acc[ii][0] * scale, acc[ii][1] * scale,
                                acc[ii][2] * scale, acc[ii][3] * scale);
        float4 v1 = make_float4(acc[ii][4] * scale, acc[ii][5] * scale,
                                acc[ii][6] * scale, acc[ii][7] * scale);
        // j > row entries inside the diagonal tile are garbage here; softmax
        // never reads them and overwrites them with exact zeros for K4.
        *reinterpret_cast<float4*>(&g_S[(size_t)row * N_TOKEN + c0 + tx4])      = v0;
        *reinterpret_cast<float4*>(&g_S[(size_t)row * N_TOKEN + c0 + 64 + tx4]) = v1;
    }
}

// --------------------------- K3: causal row softmax ------------------------
__global__ __launch_bounds__(256)
void softmax_kernel() {
    int i = blockIdx.x;
    float* row = &g_S[(size_t)i * N_TOKEN];
    int len = i + 1;
    int t = threadIdx.x;
    __shared__ float red[256];

    float m = -3.0e38f;
    for (int j = t; j < len; j += 256) m = fmaxf(m, row[j]);
    red[t] = m; __syncthreads();
#pragma unroll
    for (int s = 128; s > 0; s >>= 1) {
        if (t < s) red[t] = fmaxf(red[t], red[t + s]);
        __syncthreads();
    }
    float rowmax = red[0];
    __syncthreads();

    float sum = 0.0f;
    for (int j = t; j < len; j += 256) {
        float e = __expf(row[j] - rowmax);
        row[j] = e;
        sum += e;
    }
    red[t] = sum; __syncthreads();
#pragma unroll
    for (int s = 128; s > 0; s >>= 1) {
        if (t < s) red[t] += red[t + s];
        __syncthreads();
    }
    float inv = 1.0f / red[0];

    for (int j = t; j < len; j += 256) row[j] *= inv;

    // Zero-fill (i, end-of-own-128-block) so the PV diagonal tile reads zeros.
    int blk_end = ((i >> 7) + 1) << 7;
    for (int j = len + t; j < blk_end; j += 256) row[j] = 0.0f;
}

// --------------------------- K4: O = P V (causal k-limit) ------------------
__global__ __launch_bounds__(NTHREADS)
void pv_kernel(float* __restrict__ O) {
    __shared__ float As[BK][LDS_PAD];
    __shared__ float Bs[BK][LDS_PAD];

    int r0 = blockIdx.y * BM;
    int c0 = blockIdx.x * BN;
    int ty4 = (threadIdx.x >> 4) * 4;
    int tx4 = (threadIdx.x & 15) * 4;

    int kmax = r0 + BM;   // causal: rows in [r0, r0+128) only attend to j < r0+128
    if (kmax > N_TOKEN) kmax = N_TOKEN;

    float acc[8][8] = {};
    for (int k0 = 0; k0 < kmax; k0 += BK) {
        load_tileA_trans(As, g_S, N_TOKEN, r0, k0);
        load_tileB_nn(Bs, g_V, D_V, k0, c0);
        __syncthreads();
        compute_tile(As, Bs, acc, ty4, tx4);
        __syncthreads();
    }

#pragma unroll
    for (int ii = 0; ii < 8; ++ii) {
        int row = r0 + frag_sel(ty4, ii);
        float4 v0 = make_float4(acc[ii][0], acc[ii][1], acc[ii][2], acc[ii][3]);
        float4 v1 = make_float4(acc[ii][4], acc[ii][5], acc[ii][6], acc[ii][7]);
        *reinterpret_cast<float4*>(&O[(size_t)row * D_V + c0 + tx4])      = v0;
        *reinterpret_cast<float4*>(&O[(size_t)row * D_V + c0 + 64 + tx4]) = v1;
    }
}

// ---------------------------------------------------------------------------
extern "C" void kernel_launch(void* const* d_in, const int* in_sizes, int n_in,
                              void* d_out, int out_size) {
    const float* x  = (const float*)d_in[0];
    const float* Wq = (const float*)d_in[1];
    const float* bq = (const float*)d_in[2];
    const float* Wk = (const float*)d_in[3];
    const float* bk = (const float*)d_in[4];
    const float* Wv = (const float*)d_in[5];
    const float* bv = (const float*)d_in[6];
    float* O = (float*)d_out;

    dim3 blk(NTHREADS);

    dim3 g_qkv(D_QK / BN, N_TOKEN / BM, 3);
    qkv_kernel<<<g_qkv, blk>>>(x, Wq, bq, Wk, bk, Wv, bv);

    dim3 g_sc(N_TOKEN / BN, N_TOKEN / BM);
    scores_kernel<<<g_sc, blk>>>();

    softmax_kernel<<<N_TOKEN, 256>>>();

    dim3 g_pv(D_V / BN, N_TOKEN / BM);
    pv_kernel<<<g_pv, blk>>>(O);
}

// round 2
// speedup vs baseline: 2.0202x; 2.0202x over previous
#include <cuda_runtime.h>
#include <stdint.h>
#include <math.h>

// ---------------------------------------------------------------------------
// SelfAttention via tf32 tensor-core GEMMs (mma.sync.m16n8k8, fp32 accum).
//   K1: fused QKV projection GEMM (bias epilogue)
//   K2: S = Q K^T * scale  (lower-triangular tiles only)
//   K3: causal row softmax on S (in place, zero-fill to 128-boundary)
//   K4: O = P V            (per-row-tile causal k-limit)
// All GEMMs: 128x128x16 CTA tile, 8 warps (2x4), 64x32 warp tile,
// double-buffered smem, register-staged global loads, cvt.rna.tf32 at STS.
// ---------------------------------------------------------------------------

#define N_TOKEN 4096
#define D_IN    1024
#define D_QK    1024
#define D_V     1024

__device__ float g_Q[N_TOKEN * D_QK];
__device__ float g_K[N_TOKEN * D_QK];
__device__ float g_V[N_TOKEN * D_V];
__device__ float g_S[(size_t)N_TOKEN * N_TOKEN];

constexpr int BM = 128;
constexpr int BN = 128;
constexpr int BK = 16;
constexpr int LDA_S = 132;      // smem leading dim (floats)
constexpr int NTHREADS = 256;

__device__ __forceinline__ float f2tf32(float x) {
    uint32_t y;
    asm("cvt.rna.tf32.f32 %0, %1;" : "=r"(y) : "f"(x));
    return __uint_as_float(y);
}

__device__ __forceinline__ void mma_tf32(float d[4],
                                         uint32_t a0, uint32_t a1, uint32_t a2, uint32_t a3,
                                         uint32_t b0, uint32_t b1) {
    asm volatile(
        "mma.sync.aligned.m16n8k8.row.col.f32.tf32.tf32.f32 "
        "{%0,%1,%2,%3}, {%4,%5,%6,%7}, {%8,%9}, {%0,%1,%2,%3};"
        : "+f"(d[0]), "+f"(d[1]), "+f"(d[2]), "+f"(d[3])
        : "r"(a0), "r"(a1), "r"(a2), "r"(a3), "r"(b0), "r"(b1));
}

// ---- staged loads (gmem -> regs), and reg -> smem stores with tf32 cvt ----

// [BM x BK] tile of row-major M, transposed into smem s[k][m].
__device__ __forceinline__ void ldg_trans(float4 r[2], const float* __restrict__ M,
                                          int ld, int r0, int k0) {
    int t = threadIdx.x, row = t >> 2, cg = t & 3;
    r[0] = *reinterpret_cast<const float4*>(&M[(size_t)(r0 + row) * ld + k0 + cg * 4]);
    r[1] = *reinterpret_cast<const float4*>(&M[(size_t)(r0 + row + 64) * ld + k0 + cg * 4]);
}
__device__ __forceinline__ void sts_trans(float (*s)[LDA_S], const float4 r[2]) {
    int t = threadIdx.x, row = t >> 2, cg = t & 3;
#pragma unroll
    for (int it = 0; it < 2; ++it) {
        const float4& v = r[it];
        int rr = row + it * 64;
        s[cg * 4 + 0][rr] = f2tf32(v.x);
        s[cg * 4 + 1][rr] = f2tf32(v.y);
        s[cg * 4 + 2][rr] = f2tf32(v.z);
        s[cg * 4 + 3][rr] = f2tf32(v.w);
    }
}

// [BK x BN] tile of row-major M, straight into smem s[k][n].
__device__ __forceinline__ void ldg_nn(float4 r[2], const float* __restrict__ M,
                                       int ld, int k0, int c0) {
    int t = threadIdx.x;
#pragma unroll
    for (int it = 0; it < 2; ++it) {
        int idx = t + it * NTHREADS;
        int row = idx >> 5, c4 = idx & 31;
        r[it] = *reinterpret_cast<const float4*>(&M[(size_t)(k0 + row) * ld + c0 + c4 * 4]);
    }
}
__device__ __forceinline__ void sts_nn(float (*s)[LDA_S], const float4 r[2]) {
    int t = threadIdx.x;
#pragma unroll
    for (int it = 0; it < 2; ++it) {
        int idx = t + it * NTHREADS;
        int row = idx >> 5, c4 = idx & 31;
        float4 v = make_float4(f2tf32(r[it].x), f2tf32(r[it].y),
                               f2tf32(r[it].z), f2tf32(r[it].w));
        *reinterpret_cast<float4*>(&s[row][c4 * 4]) = v;
    }
}

// ---- per-buffer compute: 2 k-steps of 16 mma (4 mfrag x 4 nfrag) ----------
__device__ __forceinline__ void compute_buf(const float (*As)[LDA_S],
                                            const float (*Bs)[LDA_S],
                                            float acc[4][4][4],
                                            int wrow, int wcol, int g, int tig) {
#pragma unroll
    for (int ks = 0; ks < 2; ++ks) {
        int k0 = ks * 8;
        uint32_t af[4][4], bf[4][2];
#pragma unroll
        for (int mf = 0; mf < 4; ++mf) {
            int m = wrow * 64 + mf * 16 + g;
            af[mf][0] = __float_as_uint(As[k0 + tig    ][m]);
            af[mf][1] = __float_as_uint(As[k0 + tig    ][m + 8]);
            af[mf][2] = __float_as_uint(As[k0 + tig + 4][m]);
            af[mf][3] = __float_as_uint(As[k0 + tig + 4][m + 8]);
        }
#pragma unroll
        for (int nf = 0; nf < 4; ++nf) {
            int n = wcol * 32 + nf * 8 + g;
            bf[nf][0] = __float_as_uint(Bs[k0 + tig    ][n]);
            bf[nf][1] = __float_as_uint(Bs[k0 + tig + 4][n]);
        }
#pragma unroll
        for (int mf = 0; mf < 4; ++mf)
#pragma unroll
            for (int nf = 0; nf < 4; ++nf)
                mma_tf32(acc[mf][nf], af[mf][0], af[mf][1], af[mf][2], af[mf][3],
                         bf[nf][0], bf[nf][1]);
    }
}

// --------------------------- K1: QKV projections ---------------------------
__global__ __launch_bounds__(NTHREADS)
void qkv_mma_kernel(const float* __restrict__ x,
                    const float* __restrict__ Wq, const float* __restrict__ bq,
                    const float* __restrict__ Wk, const float* __restrict__ bk,
                    const float* __restrict__ Wv, const float* __restrict__ bv) {
    __shared__ float As[2][BK][LDA_S];
    __shared__ float Bs[2][BK][LDA_S];

    const float* W; const float* bias; float* C;
    if (blockIdx.z == 0)      { W = Wq; bias = bq; C = g_Q; }
    else if (blockIdx.z == 1) { W = Wk; bias = bk; C = g_K; }
    else                      { W = Wv; bias = bv; C = g_V; }

    int r0 = blockIdx.y * BM, c0 = blockIdx.x * BN;
    int lane = threadIdx.x & 31, warp = threadIdx.x >> 5;
    int wrow = warp >> 2, wcol = warp & 3;
    int g = lane >> 2, tig = lane & 3;

    float4 ra[2], rb[2];
    ldg_trans(ra, x, D_IN, r0, 0);
    ldg_nn(rb, W, D_QK, 0, c0);
    sts_trans(As[0], ra);
    sts_nn(Bs[0], rb);
    __syncthreads();

    float acc[4][4][4] = {};
    const int NIT = D_IN / BK;
    for (int it = 0; it < NIT; ++it) {
        int buf = it & 1;
        if (it + 1 < NIT) {
            ldg_trans(ra, x, D_IN, r0, (it + 1) * BK);
            ldg_nn(rb, W, D_QK, (it + 1) * BK, c0);
        }
        compute_buf(As[buf], Bs[buf], acc, wrow, wcol, g, tig);
        if (it + 1 < NIT) {
            sts_trans(As[buf ^ 1], ra);
            sts_nn(Bs[buf ^ 1], rb);
        }
        __syncthreads();
    }

#pragma unroll
    for (int mf = 0; mf < 4; ++mf) {
#pragma unroll
        for (int nf = 0; nf < 4; ++nf) {
            int row = r0 + wrow * 64 + mf * 16 + g;
            int col = c0 + wcol * 32 + nf * 8 + 2 * tig;
            float b0 = bias[col], b1 = bias[col + 1];
            float2 v0 = make_float2(acc[mf][nf][0] + b0, acc[mf][nf][1] + b1);
            float2 v1 = make_float2(acc[mf][nf][2] + b0, acc[mf][nf][3] + b1);
            *reinterpret_cast<float2*>(&C[(size_t)row * D_QK + col]) = v0;
            *reinterpret_cast<float2*>(&C[(size_t)(row + 8) * D_QK + col]) = v1;
        }
    }
}

// --------------------------- K2: S = Q K^T * scale -------------------------
__global__ __launch_bounds__(NTHREADS)
void scores_mma_kernel() {
    if (blockIdx.x > blockIdx.y) return;   // causal: lower-triangular tiles only

    __shared__ float As[2][BK][LDA_S];
    __shared__ float Bs[2][BK][LDA_S];

    int r0 = blockIdx.y * BM, c0 = blockIdx.x * BN;
    int lane = threadIdx.x & 31, warp = threadIdx.x >> 5;
    int wrow = warp >> 2, wcol = warp & 3;
    int g = lane >> 2, tig = lane & 3;
    const float scale = 1.0f / 32.0f;      // 1/sqrt(1024)

    float4 ra[2], rb[2];
    ldg_trans(ra, g_Q, D_QK, r0, 0);
    ldg_trans(rb, g_K, D_QK, c0, 0);       // NT: K tile transposed too
    sts_trans(As[0], ra);
    sts_trans(Bs[0], rb);
    __syncthreads();

    float acc[4][4][4] = {};
    const int NIT = D_QK / BK;
    for (int it = 0; it < NIT; ++it) {
        int buf = it & 1;
        if (it + 1 < NIT) {
            ldg_trans(ra, g_Q, D_QK, r0, (it + 1) * BK);
            ldg_trans(rb, g_K, D_QK, c0, (it + 1) * BK);
        }
        compute_buf(As[buf], Bs[buf], acc, wrow, wcol, g, tig);
        if (it + 1 < NIT) {
            sts_trans(As[buf ^ 1], ra);
            sts_trans(Bs[buf ^ 1], rb);
        }
        __syncthreads();
    }

#pragma unroll
    for (int mf = 0; mf < 4; ++mf) {
#pragma unroll
        for (int nf = 0; nf < 4; ++nf) {
            int row = r0 + wrow * 64 + mf * 16 + g;
            int col = c0 + wcol * 32 + nf * 8 + 2 * tig;
            float2 v0 = make_float2(acc[mf][nf][0] * scale, acc[mf][nf][1] * scale);
            float2 v1 = make_float2(acc[mf][nf][2] * scale, acc[mf][nf][3] * scale);
            *reinterpret_cast<float2*>(&g_S[(size_t)row * N_TOKEN + col]) = v0;
            *reinterpret_cast<float2*>(&g_S[(size_t)(row + 8) * N_TOKEN + col]) = v1;
        }
    }
}

// --------------------------- K3: causal row softmax ------------------------
__global__ __launch_bounds__(256)
void softmax_kernel() {
    int i = blockIdx.x;
    float* row = &g_S[(size_t)i * N_TOKEN];
    int len = i + 1;
    int t = threadIdx.x;
    __shared__ float red[256];

    float m = -3.0e38f;
    for (int j = t; j < len; j += 256) m = fmaxf(m, row[j]);
    red[t] = m; __syncthreads();
#pragma unroll
    for (int s = 128; s > 0; s >>= 1) {
        if (t < s) red[t] = fmaxf(red[t], red[t + s]);
        __syncthreads();
    }
    float rowmax = red[0];
    __syncthreads();

    float sum = 0.0f;
    for (int j = t; j < len; j += 256) {
        float e = __expf(row[j] - rowmax);
        row[j] = e;
        sum += e;
    }
    red[t] = sum; __syncthreads();
#pragma unroll
    for (int s = 128; s > 0; s >>= 1) {
        if (t < s) red[t] += red[t + s];
        __syncthreads();
    }
    float inv = 1.0f / red[0];

    for (int j = t; j < len; j += 256) row[j] *= inv;

    int blk_end = ((i >> 7) + 1) << 7;     // zero-fill to 128-boundary for K4
    for (int j = len + t; j < blk_end; j += 256) row[j] = 0.0f;
}

// --------------------------- K4: O = P V -----------------------------------
__global__ __launch_bounds__(NTHREADS)
void pv_mma_kernel(float* __restrict__ O) {
    __shared__ float As[2][BK][LDA_S];
    __shared__ float Bs[2][BK][LDA_S];

    int r0 = blockIdx.y * BM, c0 = blockIdx.x * BN;
    int lane = threadIdx.x & 31, warp = threadIdx.x >> 5;
    int wrow = warp >> 2, wcol = warp & 3;
    int g = lane >> 2, tig = lane & 3;

    int kmax = r0 + BM;                    // causal skip
    if (kmax > N_TOKEN) kmax = N_TOKEN;
    const int NIT = kmax / BK;

    float4 ra[2], rb[2];
    ldg_trans(ra, g_S, N_TOKEN, r0, 0);
    ldg_nn(rb, g_V, D_V, 0, c0);
    sts_trans(As[0], ra);
    sts_nn(Bs[0], rb);
    __syncthreads();

    float acc[4][4][4] = {};
    for (int it = 0; it < NIT; ++it) {
        int buf = it & 1;
        if (it + 1 < NIT) {
            ldg_trans(ra, g_S, N_TOKEN, r0, (it + 1) * BK);
            ldg_nn(rb, g_V, D_V, (it + 1) * BK, c0);
        }
        compute_buf(As[buf], Bs[buf], acc, wrow, wcol, g, tig);
        if (it + 1 < NIT) {
            sts_trans(As[buf ^ 1], ra);
            sts_nn(Bs[buf ^ 1], rb);
        }
        __syncthreads();
    }

#pragma unroll
    for (int mf = 0; mf < 4; ++mf) {
#pragma unroll
        for (int nf = 0; nf < 4; ++nf) {
            int row = r0 + wrow * 64 + mf * 16 + g;
            int col = c0 + wcol * 32 + nf * 8 + 2 * tig;
            float2 v0 = make_float2(acc[mf][nf][0], acc[mf][nf][1]);
            float2 v1 = make_float2(acc[mf][nf][2], acc[mf][nf][3]);
            *reinterpret_cast<float2*>(&O[(size_t)row * D_V + col]) = v0;
            *reinterpret_cast<float2*>(&O[(size_t)(row + 8) * D_V + col]) = v1;
        }
    }
}

// ---------------------------------------------------------------------------
extern "C" void kernel_launch(void* const* d_in, const int* in_sizes, int n_in,
                              void* d_out, int out_size) {
    const float* x  = (const float*)d_in[0];
    const float* Wq = (const float*)d_in[1];
    const float* bq = (const float*)d_in[2];
    const float* Wk = (const float*)d_in[3];
    const float* bk = (const float*)d_in[4];
    const float* Wv = (const float*)d_in[5];
    const float* bv = (const float*)d_in[6];
    float* O = (float*)d_out;

    dim3 blk(NTHREADS);

    dim3 g_qkv(D_QK / BN, N_TOKEN / BM, 3);
    qkv_mma_kernel<<<g_qkv, blk>>>(x, Wq, bq, Wk, bk, Wv, bv);

    dim3 g_sc(N_TOKEN / BN, N_TOKEN / BM);
    scores_mma_kernel<<<g_sc, blk>>>();

    softmax_kernel<<<N_TOKEN, 256>>>();

    dim3 g_pv(D_V / BN, N_TOKEN / BM);
    pv_mma_kernel<<<g_pv, blk>>>(O);
}

// round 4
// speedup vs baseline: 2.9605x; 1.4655x over previous
#include <cuda_runtime.h>
#include <stdint.h>

// ---------------------------------------------------------------------------
// SelfAttention, mma.sync tf32 path (tcgen05 unavailable: harness PTX target
// is sm_103 without the 'a' feature set).
//   P0: round x, Wq, Wk, Wv to tf32 in gmem (removes all cvt from mainloops)
//   K1: QKV projections (NN GEMM), epilogue: +bias, round to tf32
//   K2: S = Q K^T * scale (NT GEMM, lower-triangular tiles only)
//   K3: causal row softmax (writes tf32-rounded probs, zero-fill to 128)
//   K4: O = P V (NN GEMM, causal k-limit) -> fp32 out
// GEMM core: 128x128x32 CTA tile, 8 warps (64x32 warp tile, 16x m16n8k8),
// cp.async.cg 3-stage pipeline, conflict-free padded smem, 2 CTAs/SM.
// ---------------------------------------------------------------------------

#define N_TOKEN 4096
#define D_IN    1024
#define D_QK    1024
#define D_V     1024

__device__ float g_X[N_TOKEN * D_IN];
__device__ float g_W[3][D_IN * D_QK];
__device__ float g_Q[N_TOKEN * D_QK];
__device__ float g_K[N_TOKEN * D_QK];
__device__ float g_V[N_TOKEN * D_V];
__device__ float g_S[(size_t)N_TOKEN * N_TOKEN];

constexpr int BM = 128, BN = 128, BK = 32;
constexpr int NTH = 256;
constexpr int PAD_A = 36;    // floats/row for [128 rows][32 k] tiles
constexpr int PAD_B = 132;   // floats/row for [32 k][128 n] tiles
constexpr int TILE_A_BYTES = 128 * PAD_A * 4;          // 18432
constexpr int STG = 2 * TILE_A_BYTES;                  // A + B region per stage
constexpr int NSTAGE = 3;
constexpr int SMEM_BYTES = NSTAGE * STG;               // 110592

// ---------------- helpers --------------------------------------------------
__device__ __forceinline__ uint32_t smem_u32(const void* p) {
    uint32_t a;
    asm("{ .reg .u64 t; cvta.to.shared.u64 t, %1; cvt.u32.u64 %0, t; }"
        : "=r"(a) : "l"(p));
    return a;
}
__device__ __forceinline__ float f2tf32(float x) {
    uint32_t y;
    asm("cvt.rna.tf32.f32 %0, %1;" : "=r"(y) : "f"(x));
    return __uint_as_float(y);
}
__device__ __forceinline__ void cpa(uint32_t dst, const float* src) {
    asm volatile("cp.async.cg.shared.global [%0], [%1], 16;" :: "r"(dst), "l"(src));
}
__device__ __forceinline__ void cp_commit() {
    asm volatile("cp.async.commit_group;");
}
template <int N>
__device__ __forceinline__ void cp_wait() {
    asm volatile("cp.async.wait_group %0;" :: "n"(N));
}
__device__ __forceinline__ void mma_tf32(float d[4],
                                         uint32_t a0, uint32_t a1, uint32_t a2, uint32_t a3,
                                         uint32_t b0, uint32_t b1) {
    asm volatile(
        "mma.sync.aligned.m16n8k8.row.col.f32.tf32.tf32.f32 "
        "{%0,%1,%2,%3}, {%4,%5,%6,%7}, {%8,%9}, {%0,%1,%2,%3};"
        : "+f"(d[0]), "+f"(d[1]), "+f"(d[2]), "+f"(d[3])
        : "r"(a0), "r"(a1), "r"(a2), "r"(a3), "r"(b0), "r"(b1));
}

// ---------------- cp.async tile loaders ------------------------------------
// [128 rows x 32 floats] (A tiles, and NT B tiles): pad 36 floats/row
__device__ __forceinline__ void load_128x32(uint32_t sm, const float* __restrict__ g,
                                            int ld, int r0, int k0) {
    int t = threadIdx.x;
#pragma unroll
    for (int i = 0; i < 4; ++i) {
        int idx = t + i * NTH;          // 0..1023 chunks of 16B
        int row = idx >> 3, c = idx & 7;
        cpa(sm + (uint32_t)(row * PAD_A + c * 4) * 4,
            &g[(size_t)(r0 + row) * ld + k0 + c * 4]);
    }
}
// [32 k rows x 128 floats] (NN B tiles): pad 132 floats/row
__device__ __forceinline__ void load_32x128(uint32_t sm, const float* __restrict__ g,
                                            int ld, int k0, int c0) {
    int t = threadIdx.x;
#pragma unroll
    for (int i = 0; i < 4; ++i) {
        int idx = t + i * NTH;
        int row = idx >> 5, c = idx & 31;
        cpa(sm + (uint32_t)(row * PAD_B + c * 4) * 4,
            &g[(size_t)(k0 + row) * ld + c0 + c * 4]);
    }
}

// ---------------- pipelined GEMM mainloop ----------------------------------
// NT=false: B gmem [K,N] (NN).  NT=true: B gmem [N,K] (NT, e.g. Q.K^T).
template <bool NT>
__device__ __forceinline__ void gemm_loop(float acc[4][4][4],
                                          const float* __restrict__ A, int lda, int r0,
                                          const float* __restrict__ B, int ldb, int c0,
                                          int NIT) {
    extern __shared__ char smem[];
    uint32_t sb = smem_u32(smem);

    int warp = threadIdx.x >> 5, lane = threadIdx.x & 31;
    int wrow = warp >> 2, wcol = warp & 3;
    int gg = lane >> 2, tig = lane & 3;

    // prologue: stages 0..NSTAGE-2 in flight
#pragma unroll
    for (int s = 0; s < NSTAGE - 1; ++s) {
        if (s < NIT) {
            load_128x32(sb + s * STG, A, lda, r0, s * BK);
            if (NT) load_128x32(sb + s * STG + TILE_A_BYTES, B, ldb, c0, s * BK);
            else    load_32x128(sb + s * STG + TILE_A_BYTES, B, ldb, s * BK, c0);
        }
        cp_commit();
    }

    for (int it = 0; it < NIT; ++it) {
        cp_wait<NSTAGE - 2>();
        __syncthreads();

        int nxt = it + NSTAGE - 1;
        if (nxt < NIT) {
            int s = nxt % NSTAGE;
            load_128x32(sb + s * STG, A, lda, r0, nxt * BK);
            if (NT) load_128x32(sb + s * STG + TILE_A_BYTES, B, ldb, c0, nxt * BK);
            else    load_32x128(sb + s * STG + TILE_A_BYTES, B, ldb, nxt * BK, c0);
        }
        cp_commit();

        const float* As = (const float*)(smem + (it % NSTAGE) * STG);
        const float* Bs = (const float*)(smem + (it % NSTAGE) * STG + TILE_A_BYTES);

#pragma unroll
        for (int ks = 0; ks < 4; ++ks) {
            int kk = ks * 8;
            uint32_t af[4][4], bf[4][2];
#pragma unroll
            for (int mf = 0; mf < 4; ++mf) {
                int m = wrow * 64 + mf * 16 + gg;
                af[mf][0] = __float_as_uint(As[m * PAD_A + kk + tig]);
                af[mf][1] = __float_as_uint(As[(m + 8) * PAD_A + kk + tig]);
                af[mf][2] = __float_as_uint(As[m * PAD_A + kk + tig + 4]);
                af[mf][3] = __float_as_uint(As[(m + 8) * PAD_A + kk + tig + 4]);
            }
#pragma unroll
            for (int nf = 0; nf < 4; ++nf) {
                int n = wcol * 32 + nf * 8 + gg;
                if (NT) {
                    bf[nf][0] = __float_as_uint(Bs[n * PAD_A + kk + tig]);
                    bf[nf][1] = __float_as_uint(Bs[n * PAD_A + kk + tig + 4]);
                } else {
                    bf[nf][0] = __float_as_uint(Bs[(kk + tig) * PAD_B + n]);
                    bf[nf][1] = __float_as_uint(Bs[(kk + tig + 4) * PAD_B + n]);
                }
            }
#pragma unroll
            for (int mf = 0; mf < 4; ++mf)
#pragma unroll
                for (int nf = 0; nf < 4; ++nf)
                    mma_tf32(acc[mf][nf], af[mf][0], af[mf][1], af[mf][2], af[mf][3],
                             bf[nf][0], bf[nf][1]);
        }
    }
}

// ---------------- P0: tf32-round inputs ------------------------------------
__global__ __launch_bounds__(256)
void round_kernel(const float* __restrict__ src, float* __restrict__ dst, int n4) {
    int i = blockIdx.x * 256 + threadIdx.x;
    if (i < n4) {
        float4 v = reinterpret_cast<const float4*>(src)[i];
        float4 w = make_float4(f2tf32(v.x), f2tf32(v.y), f2tf32(v.z), f2tf32(v.w));
        reinterpret_cast<float4*>(dst)[i] = w;
    }
}

// ---------------- K1: QKV projections --------------------------------------
__global__ __launch_bounds__(NTH, 2)
void qkv_kernel(const float* __restrict__ bq, const float* __restrict__ bk,
                const float* __restrict__ bv) {
    int z = blockIdx.z;
    const float* bias = (z == 0) ? bq : (z == 1) ? bk : bv;
    float* C = (z == 0) ? g_Q : (z == 1) ? g_K : g_V;

    int r0 = blockIdx.y * BM, c0 = blockIdx.x * BN;
    float acc[4][4][4] = {};
    gemm_loop<false>(acc, g_X, D_IN, r0, g_W[z], D_QK, c0, D_IN / BK);

    int warp = threadIdx.x >> 5, lane = threadIdx.x & 31;
    int wrow = warp >> 2, wcol = warp & 3;
    int gg = lane >> 2, tig = lane & 3;
#pragma unroll
    for (int mf = 0; mf < 4; ++mf) {
#pragma unroll
        for (int nf = 0; nf < 4; ++nf) {
            int row = r0 + wrow * 64 + mf * 16 + gg;
            int col = c0 + wcol * 32 + nf * 8 + 2 * tig;
            float b0 = bias[col], b1 = bias[col + 1];
            float2 v0 = make_float2(f2tf32(acc[mf][nf][0] + b0), f2tf32(acc[mf][nf][1] + b1));
            float2 v1 = make_float2(f2tf32(acc[mf][nf][2] + b0), f2tf32(acc[mf][nf][3] + b1));
            *reinterpret_cast<float2*>(&C[(size_t)row * D_QK + col]) = v0;
            *reinterpret_cast<float2*>(&C[(size_t)(row + 8) * D_QK + col]) = v1;
        }
    }
}

// ---------------- K2: S = Q K^T * scale ------------------------------------
__global__ __launch_bounds__(NTH, 2)
void scores_kernel() {
    if (blockIdx.x > blockIdx.y) return;   // causal: lower-triangular tiles

    int r0 = blockIdx.y * BM, c0 = blockIdx.x * BN;
    float acc[4][4][4] = {};
    gemm_loop<true>(acc, g_Q, D_QK, r0, g_K, D_QK, c0, D_QK / BK);

    const float scale = 1.0f / 32.0f;      // 1/sqrt(1024)
    int warp = threadIdx.x >> 5, lane = threadIdx.x & 31;
    int wrow = warp >> 2, wcol = warp & 3;
    int gg = lane >> 2, tig = lane & 3;
#pragma unroll
    for (int mf = 0; mf < 4; ++mf) {
#pragma unroll
        for (int nf = 0; nf < 4; ++nf) {
            int row = r0 + wrow * 64 + mf * 16 + gg;
            int col = c0 + wcol * 32 + nf * 8 + 2 * tig;
            float2 v0 = make_float2(acc[mf][nf][0] * scale, acc[mf][nf][1] * scale);
            float2 v1 = make_float2(acc[mf][nf][2] * scale, acc[mf][nf][3] * scale);
            *reinterpret_cast<float2*>(&g_S[(size_t)row * N_TOKEN + col]) = v0;
            *reinterpret_cast<float2*>(&g_S[(size_t)(row + 8) * N_TOKEN + col]) = v1;
        }
    }
}

// ---------------- K3: causal row softmax -----------------------------------
__global__ __launch_bounds__(256)
void softmax_kernel() {
    int i = blockIdx.x;
    float* row = &g_S[(size_t)i * N_TOKEN];
    int len = i + 1;
    int t = threadIdx.x;
    __shared__ float red[256];

    float m = -3.0e38f;
    for (int j = t; j < len; j += 256) m = fmaxf(m, row[j]);
    red[t] = m; __syncthreads();
#pragma unroll
    for (int s = 128; s > 0; s >>= 1) {
        if (t < s) red[t] = fmaxf(red[t], red[t + s]);
        __syncthreads();
    }
    float rowmax = red[0];
    __syncthreads();

    float sum = 0.0f;
    for (int j = t; j < len; j += 256) {
        float e = __expf(row[j] - rowmax);
        row[j] = e;
        sum += e;
    }
    red[t] = sum; __syncthreads();
#pragma unroll
    for (int s = 128; s > 0; s >>= 1) {
        if (t < s) red[t] += red[t + s];
        __syncthreads();
    }
    float inv = 1.0f / red[0];

    // write tf32-rounded probabilities (exact tf32 input for the PV GEMM)
    for (int j = t; j < len; j += 256) row[j] = f2tf32(row[j] * inv);

    int blk_end = ((i >> 7) + 1) << 7;     // zero-fill to 128 boundary for K4
    for (int j = len + t; j < blk_end; j += 256) row[j] = 0.0f;
}

// ---------------- K4: O = P V ----------------------------------------------
__global__ __launch_bounds__(NTH, 2)
void pv_kernel(float* __restrict__ O) {
    int r0 = blockIdx.y * BM, c0 = blockIdx.x * BN;
    int NIT = (r0 + BM) / BK;              // causal k-limit

    float acc[4][4][4] = {};
    gemm_loop<false>(acc, g_S, N_TOKEN, r0, g_V, D_V, c0, NIT);

    int warp = threadIdx.x >> 5, lane = threadIdx.x & 31;
    int wrow = warp >> 2, wcol = warp & 3;
    int gg = lane >> 2, tig = lane & 3;
#pragma unroll
    for (int mf = 0; mf < 4; ++mf) {
#pragma unroll
        for (int nf = 0; nf < 4; ++nf) {
            int row = r0 + wrow * 64 + mf * 16 + gg;
            int col = c0 + wcol * 32 + nf * 8 + 2 * tig;
            float2 v0 = make_float2(acc[mf][nf][0], acc[mf][nf][1]);
            float2 v1 = make_float2(acc[mf][nf][2], acc[mf][nf][3]);
            *reinterpret_cast<float2*>(&O[(size_t)row * D_V + col]) = v0;
            *reinterpret_cast<float2*>(&O[(size_t)(row + 8) * D_V + col]) = v1;
        }
    }
}

// ---------------------------------------------------------------------------
extern "C" void kernel_launch(void* const* d_in, const int* in_sizes, int n_in,
                              void* d_out, int out_size) {
    const float* x  = (const float*)d_in[0];
    const float* Wq = (const float*)d_in[1];
    const float* bq = (const float*)d_in[2];
    const float* Wk = (const float*)d_in[3];
    const float* bk = (const float*)d_in[4];
    const float* Wv = (const float*)d_in[5];
    const float* bv = (const float*)d_in[6];
    float* O = (float*)d_out;

    static bool attr_done = false;
    if (!attr_done) {
        cudaFuncSetAttribute(qkv_kernel,    cudaFuncAttributeMaxDynamicSharedMemorySize, SMEM_BYTES);
        cudaFuncSetAttribute(scores_kernel, cudaFuncAttributeMaxDynamicSharedMemorySize, SMEM_BYTES);
        cudaFuncSetAttribute(pv_kernel,     cudaFuncAttributeMaxDynamicSharedMemorySize, SMEM_BYTES);
        attr_done = true;
    }

    // P0: tf32-round inputs into scratch
    float* gx; cudaGetSymbolAddress((void**)&gx, g_X);
    float* gw; cudaGetSymbolAddress((void**)&gw, g_W);
    int n4x = N_TOKEN * D_IN / 4;      // 1048576
    int n4w = D_IN * D_QK / 4;         // 262144
    round_kernel<<<(n4x + 255) / 256, 256>>>(x,  gx,                n4x);
    round_kernel<<<(n4w + 255) / 256, 256>>>(Wq, gw,                n4w);
    round_kernel<<<(n4w + 255) / 256, 256>>>(Wk, gw + D_IN * D_QK,     n4w);
    round_kernel<<<(n4w + 255) / 256, 256>>>(Wv, gw + 2 * D_IN * D_QK, n4w);

    qkv_kernel<<<dim3(D_QK / BN, N_TOKEN / BM, 3), NTH, SMEM_BYTES>>>(bq, bk, bv);

    scores_kernel<<<dim3(N_TOKEN / BN, N_TOKEN / BM), NTH, SMEM_BYTES>>>();

    softmax_kernel<<<N_TOKEN, 256>>>();

    pv_kernel<<<dim3(D_V / BN, N_TOKEN / BM), NTH, SMEM_BYTES>>>(O);
}

// round 5
// speedup vs baseline: 3.3071x; 1.1171x over previous
#include <cuda_runtime.h>
#include <stdint.h>

// ---------------------------------------------------------------------------
// SelfAttention, mma.sync tf32 (HMMA) path; all GEMMs NT with K-major tiles
// and ldmatrix fragment loads (tf32 m16n8k8 fragment layout == ldmatrix
// m8n8.x4.b16 on the 32-bit view; ldmatrix is bit-moving so pre-rounded tf32
// survives exactly).
//   P0: round x -> g_X; transpose+round Wq/Wk/Wv -> g_Wt[z] ([out][in])
//   K1: QKV projections NT (A=g_X, B=g_Wt), epilogue +bias, round tf32
//   P1: transpose V -> g_Vt ([dv][tok])
//   K2: S = Q K^T * scale NT (lower-triangular tiles only)
//   K3: causal row softmax (tf32-rounded probs, zero-fill to 128)
//   K4: O = P V NT (A=g_S, B=g_Vt, causal k-limit) -> fp32 out
// GEMM core: 128x128x32 CTA tile, 8 warps (64x32), cp.async.cg 3-stage
// pipeline, PAD=36 smem rows (conflict-free for cp.async AND ldmatrix).
// ---------------------------------------------------------------------------

#define N_TOKEN 4096
#define D_IN    1024
#define D_QK    1024
#define D_V     1024

__device__ float g_X [N_TOKEN * D_IN];
__device__ float g_Wt[3][D_IN * D_QK];                // [out][in], tf32-rounded
__device__ float g_Q [N_TOKEN * D_QK];
__device__ float g_K [N_TOKEN * D_QK];
__device__ float g_V [N_TOKEN * D_V];
__device__ float g_Vt[D_V * N_TOKEN];                 // [dv][tok]
__device__ float g_S [(size_t)N_TOKEN * N_TOKEN];

constexpr int BM = 128, BN = 128, BK = 32;
constexpr int NTH = 256;
constexpr int PAD = 36;                               // floats per 32-k row
constexpr int TILE_BYTES = 128 * PAD * 4;             // 18432
constexpr int STG = 2 * TILE_BYTES;                   // A + B per stage
constexpr int NSTAGE = 3;
constexpr int SMEM_BYTES = NSTAGE * STG;              // 110592

// ---------------- helpers --------------------------------------------------
__device__ __forceinline__ uint32_t smem_u32(const void* p) {
    uint32_t a;
    asm("{ .reg .u64 t; cvta.to.shared.u64 t, %1; cvt.u32.u64 %0, t; }"
        : "=r"(a) : "l"(p));
    return a;
}
__device__ __forceinline__ float f2tf32(float x) {
    uint32_t y;
    asm("cvt.rna.tf32.f32 %0, %1;" : "=r"(y) : "f"(x));
    return __uint_as_float(y);
}
__device__ __forceinline__ void cpa(uint32_t dst, const float* src) {
    asm volatile("cp.async.cg.shared.global [%0], [%1], 16;" :: "r"(dst), "l"(src));
}
__device__ __forceinline__ void cp_commit() { asm volatile("cp.async.commit_group;"); }
template <int N>
__device__ __forceinline__ void cp_wait() {
    asm volatile("cp.async.wait_group %0;" :: "n"(N));
}
__device__ __forceinline__ void ldsm_x4(uint32_t& r0, uint32_t& r1,
                                        uint32_t& r2, uint32_t& r3, uint32_t a) {
    asm volatile("ldmatrix.sync.aligned.m8n8.x4.shared.b16 {%0,%1,%2,%3}, [%4];"
                 : "=r"(r0), "=r"(r1), "=r"(r2), "=r"(r3) : "r"(a));
}
__device__ __forceinline__ void mma_tf32(float d[4],
                                         uint32_t a0, uint32_t a1, uint32_t a2, uint32_t a3,
                                         uint32_t b0, uint32_t b1) {
    asm volatile(
        "mma.sync.aligned.m16n8k8.row.col.f32.tf32.tf32.f32 "
        "{%0,%1,%2,%3}, {%4,%5,%6,%7}, {%8,%9}, {%0,%1,%2,%3};"
        : "+f"(d[0]), "+f"(d[1]), "+f"(d[2]), "+f"(d[3])
        : "r"(a0), "r"(a1), "r"(a2), "r"(a3), "r"(b0), "r"(b1));
}

// [128 rows x 32 floats] K-major tile loader (cp.async, PAD=36 rows)
__device__ __forceinline__ void load_128x32(uint32_t sm, const float* __restrict__ g,
                                            int ld, int r0, int k0) {
    int t = threadIdx.x;
#pragma unroll
    for (int i = 0; i < 4; ++i) {
        int idx = t + i * NTH;                  // 1024 x 16B chunks
        int row = idx >> 3, c = idx & 7;
        cpa(sm + (uint32_t)(row * PAD + c * 4) * 4,
            &g[(size_t)(r0 + row) * ld + k0 + c * 4]);
    }
}

// ---------------- NT GEMM mainloop (both operands K-major) -----------------
__device__ __forceinline__ void gemm_nt(float acc[4][4][4],
                                        const float* __restrict__ A, int lda, int r0,
                                        const float* __restrict__ B, int ldb, int c0,
                                        int NIT) {
    extern __shared__ char smem[];
    uint32_t sb = smem_u32(smem);

    int lane = threadIdx.x & 31, warp = threadIdx.x >> 5;
    int wrow = warp >> 2, wcol = warp & 3;

    // ldmatrix per-thread address bases (bytes), within a stage:
    // A (mf tile): threads 0-7 rows+0 col+0 | 8-15 rows+8 col+0
    //            | 16-23 rows+0 col+4 | 24-31 rows+8 col+4
    uint32_t aoff = ((uint32_t)(wrow * 64 + (lane & 7) + ((lane >> 3) & 1) * 8) * PAD
                     + (uint32_t)((lane >> 4) * 4)) * 4u;
    // B (nf-pair tile): threads 0-7 rows+0 col+0 | 8-15 rows+0 col+4
    //                 | 16-23 rows+8 col+0 | 24-31 rows+8 col+4
    uint32_t boff = ((uint32_t)(wcol * 32 + (lane & 7) + ((lane >> 4) & 1) * 8) * PAD
                     + (uint32_t)(((lane >> 3) & 1) * 4)) * 4u
                    + TILE_BYTES;

#pragma unroll
    for (int s = 0; s < NSTAGE - 1; ++s) {
        if (s < NIT) {
            load_128x32(sb + s * STG, A, lda, r0, s * BK);
            load_128x32(sb + s * STG + TILE_BYTES, B, ldb, c0, s * BK);
        }
        cp_commit();
    }

    for (int it = 0; it < NIT; ++it) {
        cp_wait<NSTAGE - 2>();
        __syncthreads();

        int nxt = it + NSTAGE - 1;
        if (nxt < NIT) {
            int s = nxt % NSTAGE;
            load_128x32(sb + s * STG, A, lda, r0, nxt * BK);
            load_128x32(sb + s * STG + TILE_BYTES, B, ldb, c0, nxt * BK);
        }
        cp_commit();

        uint32_t base = sb + (uint32_t)(it % NSTAGE) * STG;
        uint32_t aAddr = base + aoff;
        uint32_t bAddr = base + boff;

#pragma unroll
        for (int ks = 0; ks < 4; ++ks) {
            uint32_t af[4][4], bf[2][4];
#pragma unroll
            for (int mf = 0; mf < 4; ++mf)
                ldsm_x4(af[mf][0], af[mf][1], af[mf][2], af[mf][3],
                        aAddr + ks * 32 + mf * (16 * PAD * 4));
#pragma unroll
            for (int np = 0; np < 2; ++np)
                ldsm_x4(bf[np][0], bf[np][1], bf[np][2], bf[np][3],
                        bAddr + ks * 32 + np * (16 * PAD * 4));
#pragma unroll
            for (int mf = 0; mf < 4; ++mf)
#pragma unroll
                for (int nf = 0; nf < 4; ++nf)
                    mma_tf32(acc[mf][nf],
                             af[mf][0], af[mf][1], af[mf][2], af[mf][3],
                             bf[nf >> 1][(nf & 1) * 2], bf[nf >> 1][(nf & 1) * 2 + 1]);
        }
    }
}

// ---------------- P0: round x ----------------------------------------------
__global__ __launch_bounds__(256)
void round_kernel(const float* __restrict__ src, float* __restrict__ dst, int n4) {
    int i = blockIdx.x * 256 + threadIdx.x;
    if (i < n4) {
        float4 v = reinterpret_cast<const float4*>(src)[i];
        reinterpret_cast<float4*>(dst)[i] =
            make_float4(f2tf32(v.x), f2tf32(v.y), f2tf32(v.z), f2tf32(v.w));
    }
}

// ---------------- P0b: transpose + round W ---------------------------------
__global__ __launch_bounds__(256)
void wt_kernel(const float* __restrict__ Wq, const float* __restrict__ Wk,
               const float* __restrict__ Wv) {
    const float* src = (blockIdx.z == 0) ? Wq : (blockIdx.z == 1) ? Wk : Wv;
    float* dst = g_Wt[blockIdx.z];
    __shared__ float t[32][33];
    int x0 = blockIdx.x * 32, y0 = blockIdx.y * 32;
    int tx = threadIdx.x & 31, ty = threadIdx.x >> 5;
#pragma unroll
    for (int i = ty; i < 32; i += 8)
        t[i][tx] = f2tf32(src[(size_t)(y0 + i) * D_QK + x0 + tx]);
    __syncthreads();
#pragma unroll
    for (int i = ty; i < 32; i += 8)
        dst[(size_t)(x0 + i) * D_IN + y0 + tx] = t[tx][i];
}

// ---------------- P1: transpose V ------------------------------------------
__global__ __launch_bounds__(256)
void vt_kernel() {
    __shared__ float t[32][33];
    int x0 = blockIdx.x * 32, y0 = blockIdx.y * 32;
    int tx = threadIdx.x & 31, ty = threadIdx.x >> 5;
#pragma unroll
    for (int i = ty; i < 32; i += 8)
        t[i][tx] = g_V[(size_t)(y0 + i) * D_V + x0 + tx];
    __syncthreads();
#pragma unroll
    for (int i = ty; i < 32; i += 8)
        g_Vt[(size_t)(x0 + i) * N_TOKEN + y0 + tx] = t[tx][i];
}

// ---------------- K1: QKV projections --------------------------------------
__global__ __launch_bounds__(NTH, 2)
void qkv_kernel(const float* __restrict__ bq, const float* __restrict__ bk,
                const float* __restrict__ bv) {
    int z = blockIdx.z;
    const float* bias = (z == 0) ? bq : (z == 1) ? bk : bv;
    float* C = (z == 0) ? g_Q : (z == 1) ? g_K : g_V;

    int r0 = blockIdx.y * BM, c0 = blockIdx.x * BN;
    float acc[4][4][4] = {};
    gemm_nt(acc, g_X, D_IN, r0, g_Wt[z], D_IN, c0, D_IN / BK);

    int warp = threadIdx.x >> 5, lane = threadIdx.x & 31;
    int wrow = warp >> 2, wcol = warp & 3;
    int gg = lane >> 2, tig = lane & 3;
#pragma unroll
    for (int mf = 0; mf < 4; ++mf) {
#pragma unroll
        for (int nf = 0; nf < 4; ++nf) {
            int row = r0 + wrow * 64 + mf * 16 + gg;
            int col = c0 + wcol * 32 + nf * 8 + 2 * tig;
            float b0 = bias[col], b1 = bias[col + 1];
            float2 v0 = make_float2(f2tf32(acc[mf][nf][0] + b0), f2tf32(acc[mf][nf][1] + b1));
            float2 v1 = make_float2(f2tf32(acc[mf][nf][2] + b0), f2tf32(acc[mf][nf][3] + b1));
            *reinterpret_cast<float2*>(&C[(size_t)row * D_QK + col]) = v0;
            *reinterpret_cast<float2*>(&C[(size_t)(row + 8) * D_QK + col]) = v1;
        }
    }
}

// ---------------- K2: S = Q K^T * scale ------------------------------------
__global__ __launch_bounds__(NTH, 2)
void scores_kernel() {
    if (blockIdx.x > blockIdx.y) return;       // causal: lower-triangular tiles

    int r0 = blockIdx.y * BM, c0 = blockIdx.x * BN;
    float acc[4][4][4] = {};
    gemm_nt(acc, g_Q, D_QK, r0, g_K, D_QK, c0, D_QK / BK);

    const float scale = 1.0f / 32.0f;          // 1/sqrt(1024)
    int warp = threadIdx.x >> 5, lane = threadIdx.x & 31;
    int wrow = warp >> 2, wcol = warp & 3;
    int gg = lane >> 2, tig = lane & 3;
#pragma unroll
    for (int mf = 0; mf < 4; ++mf) {
#pragma unroll
        for (int nf = 0; nf < 4; ++nf) {
            int row = r0 + wrow * 64 + mf * 16 + gg;
            int col = c0 + wcol * 32 + nf * 8 + 2 * tig;
            float2 v0 = make_float2(acc[mf][nf][0] * scale, acc[mf][nf][1] * scale);
            float2 v1 = make_float2(acc[mf][nf][2] * scale, acc[mf][nf][3] * scale);
            *reinterpret_cast<float2*>(&g_S[(size_t)row * N_TOKEN + col]) = v0;
            *reinterpret_cast<float2*>(&g_S[(size_t)(row + 8) * N_TOKEN + col]) = v1;
        }
    }
}

// ---------------- K3: causal row softmax -----------------------------------
__global__ __launch_bounds__(256)
void softmax_kernel() {
    int i = blockIdx.x;
    float* row = &g_S[(size_t)i * N_TOKEN];
    int len = i + 1;
    int t = threadIdx.x;
    __shared__ float red[256];

    float m = -3.0e38f;
    for (int j = t; j < len; j += 256) m = fmaxf(m, row[j]);
    red[t] = m; __syncthreads();
#pragma unroll
    for (int s = 128; s > 0; s >>= 1) {
        if (t < s) red[t] = fmaxf(red[t], red[t + s]);
        __syncthreads();
    }
    float rowmax = red[0];
    __syncthreads();

    float sum = 0.0f;
    for (int j = t; j < len; j += 256) {
        float e = __expf(row[j] - rowmax);
        row[j] = e;
        sum += e;
    }
    red[t] = sum; __syncthreads();
#pragma unroll
    for (int s = 128; s > 0; s >>= 1) {
        if (t < s) red[t] += red[t + s];
        __syncthreads();
    }
    float inv = 1.0f / red[0];

    for (int j = t; j < len; j += 256) row[j] = f2tf32(row[j] * inv);

    int blk_end = ((i >> 7) + 1) << 7;         // zero-fill to 128 for K4
    for (int j = len + t; j < blk_end; j += 256) row[j] = 0.0f;
}

// ---------------- K4: O = P V ----------------------------------------------
__global__ __launch_bounds__(NTH, 2)
void pv_kernel(float* __restrict__ O) {
    int r0 = blockIdx.y * BM, c0 = blockIdx.x * BN;
    int NIT = (r0 + BM) / BK;                  // causal k-limit

    float acc[4][4][4] = {};
    gemm_nt(acc, g_S, N_TOKEN, r0, g_Vt, N_TOKEN, c0, NIT);

    int warp = threadIdx.x >> 5, lane = threadIdx.x & 31;
    int wrow = warp >> 2, wcol = warp & 3;
    int gg = lane >> 2, tig = lane & 3;
#pragma unroll
    for (int mf = 0; mf < 4; ++mf) {
#pragma unroll
        for (int nf = 0; nf < 4; ++nf) {
            int row = r0 + wrow * 64 + mf * 16 + gg;
            int col = c0 + wcol * 32 + nf * 8 + 2 * tig;
            float2 v0 = make_float2(acc[mf][nf][0], acc[mf][nf][1]);
            float2 v1 = make_float2(acc[mf][nf][2], acc[mf][nf][3]);
            *reinterpret_cast<float2*>(&O[(size_t)row * D_V + col]) = v0;
            *reinterpret_cast<float2*>(&O[(size_t)(row + 8) * D_V + col]) = v1;
        }
    }
}

// ---------------------------------------------------------------------------
extern "C" void kernel_launch(void* const* d_in, const int* in_sizes, int n_in,
                              void* d_out, int out_size) {
    const float* x  = (const float*)d_in[0];
    const float* Wq = (const float*)d_in[1];
    const float* bq = (const float*)d_in[2];
    const float* Wk = (const float*)d_in[3];
    const float* bk = (const float*)d_in[4];
    const float* Wv = (const float*)d_in[5];
    const float* bv = (const float*)d_in[6];
    float* O = (float*)d_out;

    static bool attr_done = false;
    if (!attr_done) {
        cudaFuncSetAttribute(qkv_kernel,    cudaFuncAttributeMaxDynamicSharedMemorySize, SMEM_BYTES);
        cudaFuncSetAttribute(scores_kernel, cudaFuncAttributeMaxDynamicSharedMemorySize, SMEM_BYTES);
        cudaFuncSetAttribute(pv_kernel,     cudaFuncAttributeMaxDynamicSharedMemorySize, SMEM_BYTES);
        attr_done = true;
    }

    float* gx; cudaGetSymbolAddress((void**)&gx, g_X);
    int n4x = N_TOKEN * D_IN / 4;
    round_kernel<<<(n4x + 255) / 256, 256>>>(x, gx, n4x);
    wt_kernel<<<dim3(32, 32, 3), 256>>>(Wq, Wk, Wv);

    qkv_kernel<<<dim3(D_QK / BN, N_TOKEN / BM, 3), NTH, SMEM_BYTES>>>(bq, bk, bv);

    vt_kernel<<<dim3(D_V / 32, N_TOKEN / 32), 256>>>();

    scores_kernel<<<dim3(N_TOKEN / BN, N_TOKEN / BM), NTH, SMEM_BYTES>>>();

    softmax_kernel<<<N_TOKEN, 256>>>();

    pv_kernel<<<dim3(D_V / BN, N_TOKEN / BM), NTH, SMEM_BYTES>>>(O);
}

// round 6
// speedup vs baseline: 3.7476x; 1.1332x over previous
#include <cuda_runtime.h>
#include <stdint.h>

// ---------------------------------------------------------------------------
// SelfAttention, mma.sync tf32 (HMMA) NT GEMMs + ldmatrix fragments.
//   P0 : round x -> g_X; transpose+round W -> g_Wt
//   K1 : QKV projections (epilogue +bias, tf32 round)
//   P1 : transpose V -> g_Vt
//   K2 : S = Q K^T * scale (lower-tri tiles), epilogue also atomicMax row max
//        (flipped-uint keys: order-invariant => deterministic)
//   K3 : softmax single pass: P = tf32(exp(s-max)), rowsum -> g_inv (1/sum)
//   K4 : PV split-K: 640 balanced chunks (<=32 k-iters) -> partials
//   K5 : reduce partials, scale by g_inv -> O
// GEMM core: 128x128x32 tile, 8 warps, cp.async 3-stage, PAD=36 smem.
// ---------------------------------------------------------------------------

#define N_TOKEN 4096
#define D_IN    1024
#define D_QK    1024
#define D_V     1024

__device__ float    g_X [N_TOKEN * D_IN];
__device__ float    g_Wt[3][D_IN * D_QK];        // [out][in], tf32-rounded
__device__ float    g_Q [N_TOKEN * D_QK];
__device__ float    g_K [N_TOKEN * D_QK];
__device__ float    g_V [N_TOKEN * D_V];
__device__ float    g_Vt[D_V * N_TOKEN];         // [dv][tok]
__device__ float    g_S [(size_t)N_TOKEN * N_TOKEN];
__device__ unsigned g_rowmax[N_TOKEN];           // flipped-uint float keys
__device__ float    g_inv[N_TOKEN];              // 1/rowsum
__device__ float    g_part[80 * 8 * 128 * 128];  // PV split-K partials (40MB)

constexpr int BM = 128, BN = 128, BK = 32;
constexpr int NTH = 256;
constexpr int PAD = 36;
constexpr int TILE_BYTES = 128 * PAD * 4;        // 18432
constexpr int STG = 2 * TILE_BYTES;
constexpr int NSTAGE = 3;
constexpr int SMEM_BYTES = NSTAGE * STG;         // 110592

// PV split-K chunk tables: row-tile i has ceil((i+1)/8) chunks of <=32 k-iters.
__constant__ int PV_ROW[80] = {
    0,1,2,3,4,5,6,7,
    8,8,9,9,10,10,11,11,12,12,13,13,14,14,15,15,
    16,16,16,17,17,17,18,18,18,19,19,19,20,20,20,21,21,21,22,22,22,23,23,23,
    24,24,24,24,25,25,25,25,26,26,26,26,27,27,27,27,
    28,28,28,28,29,29,29,29,30,30,30,30,31,31,31,31};
__constant__ int PV_CHK[80] = {
    0,0,0,0,0,0,0,0,
    0,1,0,1,0,1,0,1,0,1,0,1,0,1,0,1,
    0,1,2,0,1,2,0,1,2,0,1,2,0,1,2,0,1,2,0,1,2,0,1,2,
    0,1,2,3,0,1,2,3,0,1,2,3,0,1,2,3,
    0,1,2,3,0,1,2,3,0,1,2,3,0,1,2,3};
__constant__ int PV_BASE[32] = {0,1,2,3,4,5,6,7,8,10,12,14,16,18,20,22,
                                24,27,30,33,36,39,42,45,48,52,56,60,64,68,72,76};
__constant__ int PV_NCH[32]  = {1,1,1,1,1,1,1,1,2,2,2,2,2,2,2,2,
                                3,3,3,3,3,3,3,3,4,4,4,4,4,4,4,4};

// ---------------- helpers --------------------------------------------------
__device__ __forceinline__ uint32_t smem_u32(const void* p) {
    uint32_t a;
    asm("{ .reg .u64 t; cvta.to.shared.u64 t, %1; cvt.u32.u64 %0, t; }"
        : "=r"(a) : "l"(p));
    return a;
}
__device__ __forceinline__ float f2tf32(float x) {
    uint32_t y;
    asm("cvt.rna.tf32.f32 %0, %1;" : "=r"(y) : "f"(x));
    return __uint_as_float(y);
}
__device__ __forceinline__ unsigned fkey(float f) {        // order-preserving
    unsigned b = __float_as_uint(f);
    return (b & 0x80000000u) ? ~b : (b | 0x80000000u);
}
__device__ __forceinline__ float fdekey(unsigned k) {
    unsigned b = (k & 0x80000000u) ? (k ^ 0x80000000u) : ~k;
    return __uint_as_float(b);
}
__device__ __forceinline__ void cpa(uint32_t dst, const float* src) {
    asm volatile("cp.async.cg.shared.global [%0], [%1], 16;" :: "r"(dst), "l"(src));
}
__device__ __forceinline__ void cp_commit() { asm volatile("cp.async.commit_group;"); }
template <int N>
__device__ __forceinline__ void cp_wait() {
    asm volatile("cp.async.wait_group %0;" :: "n"(N));
}
__device__ __forceinline__ void ldsm_x4(uint32_t& r0, uint32_t& r1,
                                        uint32_t& r2, uint32_t& r3, uint32_t a) {
    asm volatile("ldmatrix.sync.aligned.m8n8.x4.shared.b16 {%0,%1,%2,%3}, [%4];"
                 : "=r"(r0), "=r"(r1), "=r"(r2), "=r"(r3) : "r"(a));
}
__device__ __forceinline__ void mma_tf32(float d[4],
                                         uint32_t a0, uint32_t a1, uint32_t a2, uint32_t a3,
                                         uint32_t b0, uint32_t b1) {
    asm volatile(
        "mma.sync.aligned.m16n8k8.row.col.f32.tf32.tf32.f32 "
        "{%0,%1,%2,%3}, {%4,%5,%6,%7}, {%8,%9}, {%0,%1,%2,%3};"
        : "+f"(d[0]), "+f"(d[1]), "+f"(d[2]), "+f"(d[3])
        : "r"(a0), "r"(a1), "r"(a2), "r"(a3), "r"(b0), "r"(b1));
}

__device__ __forceinline__ void load_128x32(uint32_t sm, const float* __restrict__ g,
                                            int ld, int r0, int k0) {
    int t = threadIdx.x;
#pragma unroll
    for (int i = 0; i < 4; ++i) {
        int idx = t + i * NTH;
        int row = idx >> 3, c = idx & 7;
        cpa(sm + (uint32_t)(row * PAD + c * 4) * 4,
            &g[(size_t)(r0 + row) * ld + k0 + c * 4]);
    }
}

// ---------------- NT GEMM mainloop (both operands K-major) -----------------
__device__ __forceinline__ void gemm_nt(float acc[4][4][4],
                                        const float* __restrict__ A, int lda, int r0,
                                        const float* __restrict__ B, int ldb, int c0,
                                        int NIT) {
    extern __shared__ char smem[];
    uint32_t sb = smem_u32(smem);

    int lane = threadIdx.x & 31, warp = threadIdx.x >> 5;
    int wrow = warp >> 2, wcol = warp & 3;

    uint32_t aoff = ((uint32_t)(wrow * 64 + (lane & 7) + ((lane >> 3) & 1) * 8) * PAD
                     + (uint32_t)((lane >> 4) * 4)) * 4u;
    uint32_t boff = ((uint32_t)(wcol * 32 + (lane & 7) + ((lane >> 4) & 1) * 8) * PAD
                     + (uint32_t)(((lane >> 3) & 1) * 4)) * 4u
                    + TILE_BYTES;

#pragma unroll
    for (int s = 0; s < NSTAGE - 1; ++s) {
        if (s < NIT) {
            load_128x32(sb + s * STG, A, lda, r0, s * BK);
            load_128x32(sb + s * STG + TILE_BYTES, B, ldb, c0, s * BK);
        }
        cp_commit();
    }

    for (int it = 0; it < NIT; ++it) {
        cp_wait<NSTAGE - 2>();
        __syncthreads();

        int nxt = it + NSTAGE - 1;
        if (nxt < NIT) {
            int s = nxt % NSTAGE;
            load_128x32(sb + s * STG, A, lda, r0, nxt * BK);
            load_128x32(sb + s * STG + TILE_BYTES, B, ldb, c0, nxt * BK);
        }
        cp_commit();

        uint32_t base = sb + (uint32_t)(it % NSTAGE) * STG;
        uint32_t aAddr = base + aoff;
        uint32_t bAddr = base + boff;

#pragma unroll
        for (int ks = 0; ks < 4; ++ks) {
            uint32_t af[4][4], bf[2][4];
#pragma unroll
            for (int mf = 0; mf < 4; ++mf)
                ldsm_x4(af[mf][0], af[mf][1], af[mf][2], af[mf][3],
                        aAddr + ks * 32 + mf * (16 * PAD * 4));
#pragma unroll
            for (int np = 0; np < 2; ++np)
                ldsm_x4(bf[np][0], bf[np][1], bf[np][2], bf[np][3],
                        bAddr + ks * 32 + np * (16 * PAD * 4));
#pragma unroll
            for (int mf = 0; mf < 4; ++mf)
#pragma unroll
                for (int nf = 0; nf < 4; ++nf)
                    mma_tf32(acc[mf][nf],
                             af[mf][0], af[mf][1], af[mf][2], af[mf][3],
                             bf[nf >> 1][(nf & 1) * 2], bf[nf >> 1][(nf & 1) * 2 + 1]);
        }
    }
}

// ---------------- P0: round x / transpose W / init rowmax ------------------
__global__ __launch_bounds__(256)
void round_kernel(const float* __restrict__ src, float* __restrict__ dst, int n4) {
    int i = blockIdx.x * 256 + threadIdx.x;
    if (i < n4) {
        float4 v = reinterpret_cast<const float4*>(src)[i];
        reinterpret_cast<float4*>(dst)[i] =
            make_float4(f2tf32(v.x), f2tf32(v.y), f2tf32(v.z), f2tf32(v.w));
    }
}

__global__ __launch_bounds__(256)
void wt_kernel(const float* __restrict__ Wq, const float* __restrict__ Wk,
               const float* __restrict__ Wv) {
    const float* src = (blockIdx.z == 0) ? Wq : (blockIdx.z == 1) ? Wk : Wv;
    float* dst = g_Wt[blockIdx.z];
    __shared__ float t[32][33];
    int x0 = blockIdx.x * 32, y0 = blockIdx.y * 32;
    int tx = threadIdx.x & 31, ty = threadIdx.x >> 5;
#pragma unroll
    for (int i = ty; i < 32; i += 8)
        t[i][tx] = f2tf32(src[(size_t)(y0 + i) * D_QK + x0 + tx]);
    __syncthreads();
#pragma unroll
    for (int i = ty; i < 32; i += 8)
        dst[(size_t)(x0 + i) * D_IN + y0 + tx] = t[tx][i];
}

__global__ __launch_bounds__(256)
void init_rowmax_kernel() {
    int i = blockIdx.x * 256 + threadIdx.x;
    if (i < N_TOKEN) g_rowmax[i] = 0u;   // below any real key; always overwritten
}

__global__ __launch_bounds__(256)
void vt_kernel() {
    __shared__ float t[32][33];
    int x0 = blockIdx.x * 32, y0 = blockIdx.y * 32;
    int tx = threadIdx.x & 31, ty = threadIdx.x >> 5;
#pragma unroll
    for (int i = ty; i < 32; i += 8)
        t[i][tx] = g_V[(size_t)(y0 + i) * D_V + x0 + tx];
    __syncthreads();
#pragma unroll
    for (int i = ty; i < 32; i += 8)
        g_Vt[(size_t)(x0 + i) * N_TOKEN + y0 + tx] = t[tx][i];
}

// ---------------- K1: QKV projections --------------------------------------
__global__ __launch_bounds__(NTH, 2)
void qkv_kernel(const float* __restrict__ bq, const float* __restrict__ bk,
                const float* __restrict__ bv) {
    int z = blockIdx.z;
    const float* bias = (z == 0) ? bq : (z == 1) ? bk : bv;
    float* C = (z == 0) ? g_Q : (z == 1) ? g_K : g_V;

    int r0 = blockIdx.y * BM, c0 = blockIdx.x * BN;
    float acc[4][4][4] = {};
    gemm_nt(acc, g_X, D_IN, r0, g_Wt[z], D_IN, c0, D_IN / BK);

    int warp = threadIdx.x >> 5, lane = threadIdx.x & 31;
    int wrow = warp >> 2, wcol = warp & 3;
    int gg = lane >> 2, tig = lane & 3;
#pragma unroll
    for (int mf = 0; mf < 4; ++mf) {
#pragma unroll
        for (int nf = 0; nf < 4; ++nf) {
            int row = r0 + wrow * 64 + mf * 16 + gg;
            int col = c0 + wcol * 32 + nf * 8 + 2 * tig;
            float b0 = bias[col], b1 = bias[col + 1];
            float2 v0 = make_float2(f2tf32(acc[mf][nf][0] + b0), f2tf32(acc[mf][nf][1] + b1));
            float2 v1 = make_float2(f2tf32(acc[mf][nf][2] + b0), f2tf32(acc[mf][nf][3] + b1));
            *reinterpret_cast<float2*>(&C[(size_t)row * D_QK + col]) = v0;
            *reinterpret_cast<float2*>(&C[(size_t)(row + 8) * D_QK + col]) = v1;
        }
    }
}

// ---------------- K2: S = Q K^T * scale + row-max ---------------------------
__global__ __launch_bounds__(NTH, 2)
void scores_kernel() {
    if (blockIdx.x > blockIdx.y) return;       // causal: lower-triangular tiles

    int r0 = blockIdx.y * BM, c0 = blockIdx.x * BN;
    float acc[4][4][4] = {};
    gemm_nt(acc, g_Q, D_QK, r0, g_K, D_QK, c0, D_QK / BK);

    const float scale = 1.0f / 32.0f;
    bool diag = (blockIdx.x == blockIdx.y);
    int warp = threadIdx.x >> 5, lane = threadIdx.x & 31;
    int wrow = warp >> 2, wcol = warp & 3;
    int gg = lane >> 2, tig = lane & 3;

#pragma unroll
    for (int mf = 0; mf < 4; ++mf) {
#pragma unroll
        for (int nf = 0; nf < 4; ++nf) {
            int row = r0 + wrow * 64 + mf * 16 + gg;
            int col = c0 + wcol * 32 + nf * 8 + 2 * tig;
            float2 v0 = make_float2(acc[mf][nf][0] * scale, acc[mf][nf][1] * scale);
            float2 v1 = make_float2(acc[mf][nf][2] * scale, acc[mf][nf][3] * scale);
            *reinterpret_cast<float2*>(&g_S[(size_t)row * N_TOKEN + col]) = v0;
            *reinterpret_cast<float2*>(&g_S[(size_t)(row + 8) * N_TOKEN + col]) = v1;
        }
    }

    // per-row max (diag tiles: only cols <= row), quad-reduced, atomicMax.
#pragma unroll
    for (int mf = 0; mf < 4; ++mf) {
#pragma unroll
        for (int h = 0; h < 2; ++h) {
            int row = r0 + wrow * 64 + mf * 16 + gg + 8 * h;
            float mx = -3.0e38f;
#pragma unroll
            for (int nf = 0; nf < 4; ++nf) {
#pragma unroll
                for (int k2 = 0; k2 < 2; ++k2) {
                    int col = c0 + wcol * 32 + nf * 8 + 2 * tig + k2;
                    float v = acc[mf][nf][2 * h + k2] * scale;
                    if (!diag || col <= row) mx = fmaxf(mx, v);
                }
            }
            mx = fmaxf(mx, __shfl_xor_sync(0xFFFFFFFFu, mx, 1));
            mx = fmaxf(mx, __shfl_xor_sync(0xFFFFFFFFu, mx, 2));
            if (tig == 0) atomicMax(&g_rowmax[row], fkey(mx));
        }
    }
}

// ---------------- K3: softmax single pass ----------------------------------
__global__ __launch_bounds__(256)
void softmax_kernel() {
    int i = blockIdx.x;
    float* row = &g_S[(size_t)i * N_TOKEN];
    int len = i + 1;
    int t = threadIdx.x;
    __shared__ float red[256];

    float rowmax = fdekey(g_rowmax[i]);

    float sum = 0.0f;
    for (int j = t; j < len; j += 256) {
        float e = __expf(row[j] - rowmax);
        row[j] = f2tf32(e);                 // unnormalized tf32 probabilities
        sum += e;
    }
    red[t] = sum; __syncthreads();
#pragma unroll
    for (int s = 128; s > 0; s >>= 1) {
        if (t < s) red[t] += red[t + s];
        __syncthreads();
    }
    if (t == 0) g_inv[i] = 1.0f / red[0];

    int blk_end = ((i >> 7) + 1) << 7;      // zero-fill to 128 boundary for K4
    for (int j = len + t; j < blk_end; j += 256) row[j] = 0.0f;
}

// ---------------- K4: PV split-K chunks ------------------------------------
__global__ __launch_bounds__(NTH, 2)
void pv_kernel() {
    int e = blockIdx.y;
    int i = PV_ROW[e], s = PV_CHK[e];
    int r0 = i * BM, c0 = blockIdx.x * BN;
    int it0 = s * 32;
    int itend = min(it0 + 32, 4 * (i + 1));
    int NIT = itend - it0;

    float acc[4][4][4] = {};
    gemm_nt(acc, g_S + (size_t)it0 * BK, N_TOKEN, r0,
            g_Vt + (size_t)it0 * BK, N_TOKEN, c0, NIT);

    float* part = g_part + ((size_t)e * 8 + blockIdx.x) * (128 * 128);
    int warp = threadIdx.x >> 5, lane = threadIdx.x & 31;
    int wrow = warp >> 2, wcol = warp & 3;
    int gg = lane >> 2, tig = lane & 3;
#pragma unroll
    for (int mf = 0; mf < 4; ++mf) {
#pragma unroll
        for (int nf = 0; nf < 4; ++nf) {
            int rl = wrow * 64 + mf * 16 + gg;
            int cl = wcol * 32 + nf * 8 + 2 * tig;
            *reinterpret_cast<float2*>(&part[rl * 128 + cl]) =
                make_float2(acc[mf][nf][0], acc[mf][nf][1]);
            *reinterpret_cast<float2*>(&part[(rl + 8) * 128 + cl]) =
                make_float2(acc[mf][nf][2], acc[mf][nf][3]);
        }
    }
}

// ---------------- K5: reduce partials + normalize -> O ---------------------
__global__ __launch_bounds__(256)
void pv_reduce_kernel(float* __restrict__ O) {
    int row = blockIdx.x;                  // one block per output row
    int t = threadIdx.x;                   // 256 threads x 4 cols = 1024
    int i = row >> 7, rl = row & 127;
    int base = PV_BASE[i], n = PV_NCH[i];
    int col = t * 4;
    int ct = col >> 7, cl = col & 127;

    float4 acc = make_float4(0.f, 0.f, 0.f, 0.f);
    for (int s = 0; s < n; ++s) {
        const float4 v = *reinterpret_cast<const float4*>(
            &g_part[((size_t)(base + s) * 8 + ct) * (128 * 128) + rl * 128 + cl]);
        acc.x += v.x; acc.y += v.y; acc.z += v.z; acc.w += v.w;
    }
    float inv = g_inv[row];
    acc.x *= inv; acc.y *= inv; acc.z *= inv; acc.w *= inv;
    *reinterpret_cast<float4*>(&O[(size_t)row * D_V + col]) = acc;
}

// ---------------------------------------------------------------------------
extern "C" void kernel_launch(void* const* d_in, const int* in_sizes, int n_in,
                              void* d_out, int out_size) {
    const float* x  = (const float*)d_in[0];
    const float* Wq = (const float*)d_in[1];
    const float* bq = (const float*)d_in[2];
    const float* Wk = (const float*)d_in[3];
    const float* bk = (const float*)d_in[4];
    const float* Wv = (const float*)d_in[5];
    const float* bv = (const float*)d_in[6];
    float* O = (float*)d_out;

    static bool attr_done = false;
    if (!attr_done) {
        cudaFuncSetAttribute(qkv_kernel,    cudaFuncAttributeMaxDynamicSharedMemorySize, SMEM_BYTES);
        cudaFuncSetAttribute(scores_kernel, cudaFuncAttributeMaxDynamicSharedMemorySize, SMEM_BYTES);
        cudaFuncSetAttribute(pv_kernel,     cudaFuncAttributeMaxDynamicSharedMemorySize, SMEM_BYTES);
        attr_done = true;
    }

    float* gx; cudaGetSymbolAddress((void**)&gx, g_X);
    int n4x = N_TOKEN * D_IN / 4;
    init_rowmax_kernel<<<16, 256>>>();
    round_kernel<<<(n4x + 255) / 256, 256>>>(x, gx, n4x);
    wt_kernel<<<dim3(32, 32, 3), 256>>>(Wq, Wk, Wv);

    qkv_kernel<<<dim3(D_QK / BN, N_TOKEN / BM, 3), NTH, SMEM_BYTES>>>(bq, bk, bv);

    vt_kernel<<<dim3(D_V / 32, N_TOKEN / 32), 256>>>();

    scores_kernel<<<dim3(N_TOKEN / BN, N_TOKEN / BM), NTH, SMEM_BYTES>>>();

    softmax_kernel<<<N_TOKEN, 256>>>();

    pv_kernel<<<dim3(8, 80), NTH, SMEM_BYTES>>>();

    pv_reduce_kernel<<<N_TOKEN, 256>>>(O);
}